// round 8
// baseline (speedup 1.0000x reference)
#include <cuda_runtime.h>
#include <cuda_bf16.h>
#include <cstdint>

// ---------------------------------------------------------------------------
// ScaleSelfAttention: out = x + gamma * softmax((xWf)(xWg)^T) (xWh)
// B=4, N=4096, C=256, d=32
//  proj_kernel: h bf16 transposed [b][c][tok]; f,g as bf16 hi/lo split
//               extended operands (K=96): f_ext=[hi|hi|lo], g_ext=[hi|lo|hi].
//  attn_kernel: 64 q/CTA, 32-key tiles, 128 iterations, ONE barrier/tile.
//               S via mma.sync bf16 (K=96); P = exp(S - mhat) with
//               mhat = ||f||*max||g||; O += H.P^T (swapped operands: A=H
//               unique 32-ch slab/warp, B=P shared). Triple-buffered HS/GE,
//               double PB -> O(kt) overlaps S(kt+1) across warps.
// ---------------------------------------------------------------------------

#define BATCH 4
#define NTOK  4096
#define CDIM  256
#define DDIM  32

__device__ __nv_bfloat16 g_fe[BATCH * NTOK * 96];
__device__ __nv_bfloat16 g_ge[BATCH * NTOK * 96];
__device__ __nv_bfloat16 g_ht[BATCH * CDIM * NTOK];
__device__ float         g_fn2[BATCH * NTOK];
__device__ float         g_g2blk[256];

typedef unsigned long long ull;

__device__ __forceinline__ void fma2(ull& d, ull a, ull b) {
    asm("fma.rn.f32x2 %0, %1, %2, %0;" : "+l"(d) : "l"(a), "l"(b));
}
__device__ __forceinline__ ull splat2(float v) {
    ull r;
    asm("mov.b64 %0, {%1, %1};" : "=l"(r) : "f"(v));
    return r;
}
__device__ __forceinline__ float2 unpack2(ull v) {
    float2 r;
    asm("mov.b64 {%0, %1}, %2;" : "=f"(r.x), "=f"(r.y) : "l"(v));
    return r;
}
__device__ __forceinline__ uint32_t pack_bf2(float a, float b) {
    __nv_bfloat162 v = __floats2bfloat162_rn(a, b);
    return *(uint32_t*)&v;
}

// ---------------------------------------------------------------------------
// Projections (unchanged from R7)
// ---------------------------------------------------------------------------
__global__ __launch_bounds__(256) void proj_kernel(
    const float* __restrict__ x,
    const float* __restrict__ wf,
    const float* __restrict__ wg,
    const float* __restrict__ wh)
{
    __shared__ float sX[64 * 65];
    __shared__ float sW[64 * 64];
    __shared__ float sGm[2];

    const int t = threadIdx.x;
    const int rowBase = blockIdx.x * 64;
    const int bb = rowBase >> 12;
    const int tokBase = rowBase & 4095;
    const int rg = t >> 4;
    const int cg = t & 15;

    ull acc[5][8];
#pragma unroll
    for (int cc = 0; cc < 5; cc++)
#pragma unroll
        for (int q = 0; q < 8; q++) acc[cc][q] = 0ull;

    for (int kc = 0; kc < 4; kc++) {
        __syncthreads();
        for (int idx = t; idx < 4096; idx += 256) {
            int r = idx >> 6, kk = idx & 63;
            sX[r * 65 + kk] = x[(rowBase + r) * 256 + kc * 64 + kk];
        }
#pragma unroll
        for (int cc = 0; cc < 5; cc++) {
            __syncthreads();
            for (int idx = t; idx < 4096; idx += 256) {
                int kk = idx >> 6, j = idx & 63;
                int kglob = kc * 64 + kk;
                int c = cc * 64 + j;
                float w;
                if (c < 32)       w = wf[kglob * 32 + c];
                else if (c < 64)  w = wg[kglob * 32 + (c - 32)];
                else              w = wh[kglob * 256 + (c - 64)];
                sW[kk * 64 + j] = w;
            }
            __syncthreads();
#pragma unroll 4
            for (int kk = 0; kk < 64; kk++) {
                ulonglong2 bp = *(const ulonglong2*)&sW[kk * 64 + cg * 4];
                ull as[4];
#pragma unroll
                for (int i = 0; i < 4; i++)
                    as[i] = splat2(sX[(rg * 4 + i) * 65 + kk]);
#pragma unroll
                for (int i = 0; i < 4; i++) {
                    fma2(acc[cc][i * 2 + 0], as[i], bp.x);
                    fma2(acc[cc][i * 2 + 1], as[i], bp.y);
                }
            }
        }
    }

#pragma unroll
    for (int cc = 0; cc < 5; cc++) {
        __syncthreads();
#pragma unroll
        for (int i = 0; i < 4; i++) {
            float2 lo = unpack2(acc[cc][i * 2 + 0]);
            float2 hi = unpack2(acc[cc][i * 2 + 1]);
            sX[(rg * 4 + i) * 65 + cg * 4 + 0] = lo.x;
            sX[(rg * 4 + i) * 65 + cg * 4 + 1] = lo.y;
            sX[(rg * 4 + i) * 65 + cg * 4 + 2] = hi.x;
            sX[(rg * 4 + i) * 65 + cg * 4 + 3] = hi.y;
        }
        __syncthreads();

        if (cc == 0) {
            float g2 = 0.f;
            if (t < 64) {
                float f2 = 0.f;
#pragma unroll 8
                for (int k = 0; k < 32; k++) {
                    float v = sX[t * 65 + k];      f2 += v * v;
                    float w = sX[t * 65 + 32 + k]; g2 += w * w;
                }
                g_fn2[rowBase + t] = f2;
#pragma unroll
                for (int o = 16; o > 0; o >>= 1)
                    g2 = fmaxf(g2, __shfl_xor_sync(0xffffffffu, g2, o));
                if ((t & 31) == 0) sGm[t >> 5] = g2;
            }
            for (int idx = t; idx < 64 * 48; idx += 256) {
                int tok = idx / 48;
                int c0 = (idx % 48) * 2;
                size_t grow = (size_t)(bb * 4096 + tokBase + tok) * 96 + c0;
                {
                    int jf = (c0 < 64) ? (c0 & 31) : (c0 - 64);
                    float f0 = sX[tok * 65 + jf];
                    float f1 = sX[tok * 65 + jf + 1];
                    __nv_bfloat16 h0 = __float2bfloat16(f0);
                    __nv_bfloat16 h1 = __float2bfloat16(f1);
                    uint32_t w;
                    if (c0 < 64) {
                        __nv_bfloat162 v2 = {h0, h1};
                        w = *(uint32_t*)&v2;
                    } else {
                        w = pack_bf2(f0 - __bfloat162float(h0),
                                     f1 - __bfloat162float(h1));
                    }
                    *(uint32_t*)&g_fe[grow] = w;
                }
                {
                    int jg = (c0 < 32) ? c0 : ((c0 < 64) ? (c0 - 32) : (c0 - 64));
                    float ga = sX[tok * 65 + 32 + jg];
                    float gb = sX[tok * 65 + 32 + jg + 1];
                    __nv_bfloat16 h0 = __float2bfloat16(ga);
                    __nv_bfloat16 h1 = __float2bfloat16(gb);
                    uint32_t w;
                    if (c0 < 32 || c0 >= 64) {
                        __nv_bfloat162 v2 = {h0, h1};
                        w = *(uint32_t*)&v2;
                    } else {
                        w = pack_bf2(ga - __bfloat162float(h0),
                                     gb - __bfloat162float(h1));
                    }
                    *(uint32_t*)&g_ge[grow] = w;
                }
            }
        } else {
            for (int idx = t; idx < 4096; idx += 256) {
                int c = idx >> 6, tok = idx & 63;
                float v = sX[tok * 65 + c];
                g_ht[(size_t)(bb * 256 + (cc - 1) * 64 + c) * 4096 + tokBase + tok] =
                    __float2bfloat16(v);
            }
        }
    }
    __syncthreads();
    if (t == 0) g_g2blk[blockIdx.x] = fmaxf(sGm[0], sGm[1]);
}

// ---------------------------------------------------------------------------
// Attention kernel
// ---------------------------------------------------------------------------
#define HS_STRIDE 80
#define PB_STRIDE 80
#define FE_STRIDE 208
#define HS_OFF 0                     // 3 x 256*80 = 61440
#define HS_BUF 20480
#define PB_OFF 61440                 // 2 x 5120
#define PB_BUF 5120
#define FE_OFF 71680                 // 64*208 = 13312
#define GE_OFF 84992                 // 3 x 6656 = 19968
#define GE_BUF 6656
#define SLP_OFF 104960               // 512
#define SR_OFF 105472                // 32
#define SM_BYTES 105504

__device__ __forceinline__ uint32_t smem_u32(const void* p) {
    uint32_t a;
    asm("{ .reg .u64 t; cvta.to.shared.u64 t, %1; cvt.u32.u64 %0, t; }"
        : "=r"(a) : "l"(p));
    return a;
}
__device__ __forceinline__ void cp_async16(uint32_t dst, const void* src) {
    asm volatile("cp.async.cg.shared.global [%0], [%1], 16;"
                 :: "r"(dst), "l"(src) : "memory");
}
__device__ __forceinline__ void mma16816(float* d, const uint32_t* a,
                                         const uint32_t* bv) {
    asm volatile(
        "mma.sync.aligned.m16n8k16.row.col.f32.bf16.bf16.f32 "
        "{%0,%1,%2,%3}, {%4,%5,%6,%7}, {%8,%9}, {%0,%1,%2,%3};"
        : "+f"(d[0]), "+f"(d[1]), "+f"(d[2]), "+f"(d[3])
        : "r"(a[0]), "r"(a[1]), "r"(a[2]), "r"(a[3]), "r"(bv[0]), "r"(bv[1]));
}
#define LDMX4(r0, r1, r2, r3, addr) \
    asm volatile("ldmatrix.sync.aligned.m8n8.x4.shared.b16 {%0,%1,%2,%3}, [%4];" \
                 : "=r"(r0), "=r"(r1), "=r"(r2), "=r"(r3) : "r"(addr))
#define CP_COMMIT() asm volatile("cp.async.commit_group;" ::: "memory")
#define CP_WAIT(n)  asm volatile("cp.async.wait_group %0;" :: "n"(n) : "memory")

__global__ __launch_bounds__(256, 2) void attn_kernel(
    const float* __restrict__ x,
    const float* __restrict__ gamma_p,
    float* __restrict__ out)
{
    extern __shared__ char sm[];
    const int t = threadIdx.x;
    const int lane = t & 31;
    const int wid = t >> 5;
    const int gid = lane >> 2;
    const int tig = lane & 3;
    const int b = blockIdx.y;
    const int qBase = blockIdx.x * 64;
    const int qw = wid & 3;        // S: 16-query slab
    const int kw = wid >> 2;       // S: 16-key half of the 32-key tile
    const int qoff = qw * 16;
    const int cslab = wid * 32;    // O: unique channel slab

    float* sLp = (float*)(sm + SLP_OFF);
    float* sR  = (float*)(sm + SR_OFF);
    const uint32_t smbase = smem_u32(sm);

    const int r0 = qoff + gid;
    const int r1 = r0 + 8;

    // ---- prologue cp groups: G1={FE,GE0,HS0}, G2={GE1}, G3={HS1} ----
    for (int i = t; i < 768; i += 256) {
        int row = i / 12, ch = i % 12;
        cp_async16(smbase + FE_OFF + row * FE_STRIDE + ch * 16,
                   g_fe + (size_t)(b * 4096 + qBase + row) * 96 + ch * 8);
    }
#pragma unroll
    for (int i = t; i < 384; i += 256) {
        int row = i / 12, ch = i % 12;
        cp_async16(smbase + GE_OFF + row * FE_STRIDE + ch * 16,
                   g_ge + (size_t)(b * 4096 + row) * 96 + ch * 8);
    }
#pragma unroll
    for (int it = 0; it < 4; it++) {
        int idx = t + it * 256;
        int ch = idx >> 2, chunk = idx & 3;
        cp_async16(smbase + HS_OFF + ch * HS_STRIDE + chunk * 16,
                   g_ht + (size_t)(b * 256 + ch) * 4096 + chunk * 8);
    }
    CP_COMMIT();   // G1
    for (int i = t; i < 384; i += 256) {
        int row = i / 12, ch = i % 12;
        cp_async16(smbase + GE_OFF + GE_BUF + row * FE_STRIDE + ch * 16,
                   g_ge + (size_t)(b * 4096 + 32 + row) * 96 + ch * 8);
    }
    CP_COMMIT();   // G2
#pragma unroll
    for (int it = 0; it < 4; it++) {
        int idx = t + it * 256;
        int ch = idx >> 2, chunk = idx & 3;
        cp_async16(smbase + HS_OFF + HS_BUF + ch * HS_STRIDE + chunk * 16,
                   g_ht + (size_t)(b * 256 + ch) * 4096 + 32 + chunk * 8);
    }
    CP_COMMIT();   // G3

    // gmax reduce
    {
        float gv = g_g2blk[b * 64 + (t & 63)];
#pragma unroll
        for (int o = 16; o > 0; o >>= 1)
            gv = fmaxf(gv, __shfl_xor_sync(0xffffffffu, gv, o));
        if (lane == 0) sR[wid] = gv;
    }
    CP_WAIT(2);        // G1 done (FE, GE0, HS0)
    __syncthreads();   // publish G1 + sR

    float gm2 = sR[0];
#pragma unroll
    for (int w = 1; w < 8; w++) gm2 = fmaxf(gm2, sR[w]);
    const float gms = sqrtf(gm2);
    const float mh0 = sqrtf(g_fn2[b * 4096 + qBase + r0]) * gms;
    const float mh1 = sqrtf(g_fn2[b * 4096 + qBase + r1]) * gms;

    float acc[2][8][4];
#pragma unroll
    for (int mi = 0; mi < 2; mi++)
#pragma unroll
        for (int nj = 0; nj < 8; nj++)
#pragma unroll
            for (int q = 0; q < 4; q++) acc[mi][nj][q] = 0.f;

    float rsum0 = 0.f, rsum1 = 0.f;

    // lane base addresses
    const uint32_t aS = smbase + FE_OFF + (qoff + (lane & 15)) * FE_STRIDE +
                        ((lane >> 4) << 4);
    const uint32_t bS0 = smbase + GE_OFF + (kw * 16 + (lane & 7)) * FE_STRIDE +
                         ((lane >> 3) << 4);
    const uint32_t aO0 = smbase + HS_OFF + (cslab + (lane & 15)) * HS_STRIDE +
                         ((lane >> 4) << 4);
    const uint32_t bO0 = smbase + PB_OFF + (lane & 7) * PB_STRIDE +
                         ((lane >> 3) << 4);

    int hb = 0;   // kt % 3

    for (int kt = 0; kt < 128; kt++) {
        const int pb = kt & 1;
        const int nb3 = (hb == 0) ? 2 : (hb - 1);   // (kt+2) % 3

        // ---- S-MMA: m16 x n16 x k96 ----
        const uint32_t bS = bS0 + hb * GE_BUF;
        float sacc[2][4];
#pragma unroll
        for (int nb = 0; nb < 2; nb++)
#pragma unroll
            for (int q = 0; q < 4; q++) sacc[nb][q] = 0.f;

#pragma unroll
        for (int cp = 0; cp < 3; cp++) {
            uint32_t af[8];
            LDMX4(af[0], af[1], af[2], af[3], aS + cp * 64);
            LDMX4(af[4], af[5], af[6], af[7], aS + cp * 64 + 32);
#pragma unroll
            for (int nb = 0; nb < 2; nb++) {
                uint32_t bf[4];
                LDMX4(bf[0], bf[1], bf[2], bf[3],
                      bS + nb * 8 * FE_STRIDE + cp * 64);
                mma16816(sacc[nb], &af[0], &bf[0]);
                mma16816(sacc[nb], &af[4], &bf[2]);
            }
        }

        // ---- P = exp(S - mhat), store bf16 into PB[pb], row sums ----
        {
            char* PBp = sm + PB_OFF + pb * PB_BUF;
            float rs0 = 0.f, rs1 = 0.f;
#pragma unroll
            for (int nb = 0; nb < 2; nb++) {
                float p0 = __expf(sacc[nb][0] - mh0);
                float p1 = __expf(sacc[nb][1] - mh0);
                float p2 = __expf(sacc[nb][2] - mh1);
                float p3 = __expf(sacc[nb][3] - mh1);
                rs0 += p0 + p1;
                rs1 += p2 + p3;
                int colb = (kw * 16 + nb * 8 + tig * 2) * 2;
                *(uint32_t*)(PBp + r0 * PB_STRIDE + colb) = pack_bf2(p0, p1);
                *(uint32_t*)(PBp + r1 * PB_STRIDE + colb) = pack_bf2(p2, p3);
            }
            rs0 += __shfl_xor_sync(0xffffffffu, rs0, 1);
            rs0 += __shfl_xor_sync(0xffffffffu, rs0, 2);
            rs1 += __shfl_xor_sync(0xffffffffu, rs1, 1);
            rs1 += __shfl_xor_sync(0xffffffffu, rs1, 2);
            rsum0 += rs0;
            rsum1 += rs1;
        }

        // ---- cp GE(kt+2) -> GE[(kt+2)%3] (safe: S(kt-1) readers past barrier) ----
        if (kt < 126) {
            for (int i = t; i < 384; i += 256) {
                int row = i / 12, ch = i % 12;
                cp_async16(smbase + GE_OFF + nb3 * GE_BUF + row * FE_STRIDE + ch * 16,
                           g_ge + (size_t)(b * 4096 + (kt + 2) * 32 + row) * 96 + ch * 8);
            }
        }
        CP_COMMIT();   // Ga(kt)
        CP_WAIT(1);    // forces tile kt+1 data (GE+HS) complete
        __syncthreads();   // publish tile kt+1 data + P(kt); O(kt-1) done

        // ---- cp HS(kt+2) -> HS[(kt+2)%3] (safe: O(kt-1) done at barrier) ----
        if (kt < 126) {
#pragma unroll
            for (int it = 0; it < 4; it++) {
                int idx = t + it * 256;
                int ch = idx >> 2, chunk = idx & 3;
                cp_async16(smbase + HS_OFF + nb3 * HS_BUF + ch * HS_STRIDE + chunk * 16,
                           g_ht + (size_t)(b * 256 + ch) * 4096 + (kt + 2) * 32 + chunk * 8);
            }
        }
        CP_COMMIT();   // Gb(kt)

        // ---- O-MMA: A = H [32c x 32k], B = P [64q x 32k] ----
        {
            const uint32_t aO = aO0 + hb * HS_BUF;
            const uint32_t bO = bO0 + pb * PB_BUF;
            uint32_t ah[2][2][4];
#pragma unroll
            for (int mi = 0; mi < 2; mi++) {
                LDMX4(ah[mi][0][0], ah[mi][0][1], ah[mi][0][2], ah[mi][0][3],
                      aO + mi * 16 * HS_STRIDE);
                LDMX4(ah[mi][1][0], ah[mi][1][1], ah[mi][1][2], ah[mi][1][3],
                      aO + mi * 16 * HS_STRIDE + 32);
            }
#pragma unroll
            for (int nj = 0; nj < 8; nj++) {
                uint32_t bp[4];
                LDMX4(bp[0], bp[1], bp[2], bp[3], bO + nj * 8 * PB_STRIDE);
#pragma unroll
                for (int mi = 0; mi < 2; mi++) {
                    mma16816(acc[mi][nj], ah[mi][0], &bp[0]);
                    mma16816(acc[mi][nj], ah[mi][1], &bp[2]);
                }
            }
        }

        hb = (hb == 2) ? 0 : (hb + 1);
    }

    // ---- row sums ----
    if (tig == 0) {
        sLp[kw * 64 + r0] = rsum0;
        sLp[kw * 64 + r1] = rsum1;
    }
    __syncthreads();

    // ---- epilogue: out = x + gamma * O / l  (acc is [c][q]) ----
    const float gamma = *gamma_p;
#pragma unroll
    for (int nj = 0; nj < 8; nj++) {
        int q0 = nj * 8 + tig * 2;
        int q1 = q0 + 1;
        float gl0 = gamma / (sLp[q0] + sLp[64 + q0]);
        float gl1 = gamma / (sLp[q1] + sLp[64 + q1]);
        size_t rq0 = (size_t)(b * NTOK + qBase + q0) * CDIM;
        size_t rq1 = rq0 + CDIM;
#pragma unroll
        for (int mi = 0; mi < 2; mi++) {
            int c0 = cslab + mi * 16 + gid;
            int c1 = c0 + 8;
            out[rq0 + c0] = x[rq0 + c0] + gl0 * acc[mi][nj][0];
            out[rq1 + c0] = x[rq1 + c0] + gl1 * acc[mi][nj][1];
            out[rq0 + c1] = x[rq0 + c1] + gl0 * acc[mi][nj][2];
            out[rq1 + c1] = x[rq1 + c1] + gl1 * acc[mi][nj][3];
        }
    }
}

// ---------------------------------------------------------------------------
extern "C" void kernel_launch(void* const* d_in, const int* in_sizes, int n_in,
                              void* d_out, int out_size)
{
    const float* x  = (const float*)d_in[0];
    const float* wf = (const float*)d_in[1];
    const float* wg = (const float*)d_in[2];
    const float* wh = (const float*)d_in[3];
    const float* gm = (const float*)d_in[4];
    float* out = (float*)d_out;

    cudaFuncSetAttribute(attn_kernel,
                         cudaFuncAttributeMaxDynamicSharedMemorySize,
                         SM_BYTES);

    proj_kernel<<<256, 256>>>(x, wf, wg, wh);
    attn_kernel<<<dim3(64, 4), 256, SM_BYTES>>>(x, gm, out);
}